// round 15
// baseline (speedup 1.0000x reference)
#include <cuda_runtime.h>
#include <cuda_bf16.h>
#include <cstdint>
#include <climits>

// B=4, Q=V=4096, H=128; out = softmax(sqrt(128)*QK^T) with deterministic
// JAX dropout (p=0.1, key 42), then @V.
//
//  prep: fp32->int8 quantize of K (scale 127/4.5); zero per-row counters.
//  qk:   int8 mma.sync (m16n8k32) candidate search, 128x64 CTA tiles,
//        per-row running max in registers, enqueue cols within margin.
//  pv:   warp-per-row exact fp32 logits on candidates, exact softmax,
//        threefry dropout, sparse PV, normalize by 1/(0.9*Z).

#define Bn 4
#define Qn 4096
#define Vv 4096
#define Hn 128
#define NROWS (Bn * Qn)
#define CAP 192

static constexpr float SCALE_F  = 11.313708498984761f;   // sqrt(128)
static constexpr float SCALE_Q  = 28.222222f;            // 127/4.5
// margin 3.6 in raw-dot units -> int units: 3.6 * SCALE_Q^2 = 2867
#define MARGIN_INT 2900

// ---------------- static device scratch ----------------
__device__ __align__(16) uint32_t g_K8[Bn * Vv * Hn / 4];
__device__ unsigned g_cnt[NROWS];
__device__ unsigned g_col[NROWS * CAP];

// ---------------- threefry (validated R3: rel_err 4.8e-8) ---------------
__device__ __forceinline__ uint32_t rotl32(uint32_t x, int d) {
    return __funnelshift_l(x, x, d);
}
__device__ __forceinline__ uint32_t threefry_bits(uint32_t j) {
    const uint32_t K0 = 0u, K1 = 42u;
    const uint32_t K2 = 0x1BD11BDAu ^ K0 ^ K1;
    uint32_t x0 = K0, x1 = j + K1;
#define R1(r) { x0 += x1; x1 = rotl32(x1, (r)); x1 ^= x0; }
    R1(13) R1(15) R1(26) R1(6)   x0 += K1; x1 += K2 + 1u;
    R1(17) R1(29) R1(16) R1(24)  x0 += K2; x1 += K0 + 2u;
    R1(13) R1(15) R1(26) R1(6)   x0 += K0; x1 += K1 + 3u;
    R1(17) R1(29) R1(16) R1(24)  x0 += K1; x1 += K2 + 4u;
    R1(13) R1(15) R1(26) R1(6)   x0 += K2; x1 += K0 + 5u;
#undef R1
    return x0 ^ x1;
}
__device__ __forceinline__ bool keepf(uint32_t j) {
    uint32_t bits = threefry_bits(j);
    float u = __uint_as_float((bits >> 9) | 0x3f800000u) - 1.0f;
    return u < 0.9f;
}

// ---------------- helpers ----------------
__device__ __forceinline__ uint32_t s2u(const void* p) {
    return (uint32_t)__cvta_generic_to_shared(p);
}
__device__ __forceinline__ void cpasync16(uint32_t dst, const void* src) {
    asm volatile("cp.async.cg.shared.global [%0], [%1], 16;"
                 :: "r"(dst), "l"(src));
}
#define CP_COMMIT() asm volatile("cp.async.commit_group;" ::: "memory")
#define CP_WAIT0()  asm volatile("cp.async.wait_group 0;" ::: "memory")

__device__ __forceinline__ void ldmx4(uint32_t& r0, uint32_t& r1,
                                      uint32_t& r2, uint32_t& r3, uint32_t a) {
    asm volatile("ldmatrix.sync.aligned.m8n8.x4.shared.b16 {%0,%1,%2,%3},[%4];"
                 : "=r"(r0), "=r"(r1), "=r"(r2), "=r"(r3) : "r"(a));
}
__device__ __forceinline__ void mma_s8(int* c, const uint32_t* a,
                                       uint32_t b0, uint32_t b1) {
    asm volatile(
        "mma.sync.aligned.m16n8k32.row.col.s32.s8.s8.s32 "
        "{%0,%1,%2,%3},{%4,%5,%6,%7},{%8,%9},{%0,%1,%2,%3};"
        : "+r"(c[0]), "+r"(c[1]), "+r"(c[2]), "+r"(c[3])
        : "r"(a[0]), "r"(a[1]), "r"(a[2]), "r"(a[3]), "r"(b0), "r"(b1));
}
__device__ __forceinline__ uint32_t packq(float4 x) {
    int i0 = max(-127, min(127, __float2int_rn(x.x * SCALE_Q)));
    int i1 = max(-127, min(127, __float2int_rn(x.y * SCALE_Q)));
    int i2 = max(-127, min(127, __float2int_rn(x.z * SCALE_Q)));
    int i3 = max(-127, min(127, __float2int_rn(x.w * SCALE_Q)));
    return (uint32_t)(i0 & 0xff) | ((uint32_t)(i1 & 0xff) << 8) |
           ((uint32_t)(i2 & 0xff) << 16) | ((uint32_t)i3 << 24);
}

// ---------------- kernel: prep (K->int8, zero counters) -----------------
__global__ void prep_kernel(const float* __restrict__ Kg)
{
    const int ng = Bn * Vv * Hn / 4;   // 524288 groups of 4 floats
    for (int i = blockIdx.x * blockDim.x + threadIdx.x; i < ng;
         i += gridDim.x * blockDim.x)
        g_K8[i] = packq(*(const float4*)&Kg[i * 4]);
    for (int i = blockIdx.x * blockDim.x + threadIdx.x; i < NROWS;
         i += gridDim.x * blockDim.x)
        g_cnt[i] = 0u;
}

// ---------------- kernel: qk (int8 mma candidate search) ----------------
// CTA: 128 Q-rows; per k-tile 64 K-cols; 8 warps x 16 rows; K=128 (4 ks of 32).
#define LDA 144                    // padded byte stride (conflict-free 16B lds)
#define SM_Q   0                   // 128*144 = 18432
#define SM_K0  18432               // 64*144  = 9216
#define SM_K1  (18432 + 9216)
#define SMEM_QK (18432 + 18432)

__device__ __forceinline__ void load_ktile(int kt, uint32_t kbase, int b, int tid) {
    const char* src = (const char*)g_K8 + ((size_t)(b * Vv + kt * 64)) * Hn;
    #pragma unroll
    for (int e = 0; e < 2; e++) {
        int ch = tid + 256 * e;            // 512 chunks of 16B
        cpasync16(kbase + (ch >> 3) * LDA + (ch & 7) * 16, src + ch * 16);
    }
}

__global__ __launch_bounds__(256)
void qk_kernel(const float* __restrict__ Qg)
{
    extern __shared__ char smem[];
    uint32_t sb = s2u(smem);
    const int tid = threadIdx.x;
    const int wid = tid >> 5, lane = tid & 31;
    const int b = blockIdx.y, q0 = blockIdx.x * 128;
    const int m0 = wid * 16;

    // Q tile: fp32 gmem -> int8 smem (quantize in-kernel)
    {
        const float* qsrc = Qg + ((size_t)(b * Qn + q0)) * Hn;
        #pragma unroll
        for (int e = 0; e < 16; e++) {
            int g = tid + 256 * e;          // 4096 groups of 4 floats
            int row = g >> 5, c4 = (g & 31) * 4;
            *(uint32_t*)(smem + SM_Q + row * LDA + c4) =
                packq(*(const float4*)&qsrc[row * Hn + c4]);
        }
    }
    // prologue K tile
    load_ktile(0, sb + SM_K0, b, tid);
    CP_COMMIT(); CP_WAIT0();
    __syncthreads();

    // A fragments: 4 k-steps x 4 regs (same lane pattern validated in R5)
    uint32_t af[4][4];
    {
        int row = m0 + (lane & 7) + ((lane >> 3) & 1) * 8;
        int boff = (lane >> 4) * 16;
        #pragma unroll
        for (int ks = 0; ks < 4; ks++) {
            uint32_t a = sb + SM_Q + row * LDA + ks * 32 + boff;
            ldmx4(af[ks][0], af[ks][1], af[ks][2], af[ks][3], a);
        }
    }

    int rmax0 = INT_MIN / 2, rmax1 = INT_MIN / 2;
    const int grp = lane >> 2;      // 0..7
    const int qd  = lane & 3;       // 0..3
    const unsigned gr0 = (unsigned)(b * Qn + q0 + m0 + grp);
    const unsigned gr1 = gr0 + 8u;
    const int brow = lane & 7;
    const int bko  = ((lane >> 3) & 1) * 16;
    const int bno  = lane >> 4;

    int buf = 0;
    for (int t = 0; t < 64; t++) {
        if (t + 1 < 64) {
            load_ktile(t + 1, sb + (buf ? SM_K0 : SM_K1), b, tid);
            CP_COMMIT();
        }
        const uint32_t kbase = sb + (buf ? SM_K1 : SM_K0);

        int c[8][4];
        #pragma unroll
        for (int f = 0; f < 8; f++)
            #pragma unroll
            for (int j = 0; j < 4; j++) c[f][j] = 0;

        #pragma unroll
        for (int ks = 0; ks < 4; ks++) {
            #pragma unroll
            for (int fp = 0; fp < 8; fp += 2) {
                uint32_t b0, b1, b2, b3;
                uint32_t a = kbase + (8 * (fp + bno) + brow) * LDA + ks * 32 + bko;
                ldmx4(b0, b1, b2, b3, a);
                mma_s8(c[fp],     af[ks], b0, b1);
                mma_s8(c[fp + 1], af[ks], b2, b3);
            }
        }

        // epilogue: running row max (int), threshold, enqueue
        int tm0 = INT_MIN / 2, tm1 = INT_MIN / 2;
        #pragma unroll
        for (int f = 0; f < 8; f++) {
            tm0 = max(tm0, max(c[f][0], c[f][1]));
            tm1 = max(tm1, max(c[f][2], c[f][3]));
        }
        tm0 = max(tm0, __shfl_xor_sync(0xffffffffu, tm0, 1));
        tm0 = max(tm0, __shfl_xor_sync(0xffffffffu, tm0, 2));
        tm1 = max(tm1, __shfl_xor_sync(0xffffffffu, tm1, 1));
        tm1 = max(tm1, __shfl_xor_sync(0xffffffffu, tm1, 2));
        rmax0 = max(rmax0, tm0);
        rmax1 = max(rmax1, tm1);
        const int th0 = rmax0 - MARGIN_INT, th1 = rmax1 - MARGIN_INT;

        if (__any_sync(0xffffffffu, (tm0 > th0) | (tm1 > th1))) {
            #pragma unroll
            for (int f = 0; f < 8; f++) {
                unsigned colb = (unsigned)(t * 64 + 8 * f + 2 * qd);
                if (c[f][0] > th0) {
                    unsigned p = atomicAdd(&g_cnt[gr0], 1u);
                    if (p < CAP) g_col[gr0 * CAP + p] = colb;
                }
                if (c[f][1] > th0) {
                    unsigned p = atomicAdd(&g_cnt[gr0], 1u);
                    if (p < CAP) g_col[gr0 * CAP + p] = colb + 1u;
                }
                if (c[f][2] > th1) {
                    unsigned p = atomicAdd(&g_cnt[gr1], 1u);
                    if (p < CAP) g_col[gr1 * CAP + p] = colb;
                }
                if (c[f][3] > th1) {
                    unsigned p = atomicAdd(&g_cnt[gr1], 1u);
                    if (p < CAP) g_col[gr1 * CAP + p] = colb + 1u;
                }
            }
        }

        CP_WAIT0();
        __syncthreads();
        buf ^= 1;
    }
}

// ---------------- kernel: pv (warp per row, exact fp32) -----------------
__global__ __launch_bounds__(128, 8)
void pv_kernel(const float* __restrict__ Qg, const float* __restrict__ Kg,
               const float* __restrict__ Vg, float* __restrict__ Og)
{
    __shared__ unsigned scol[4][CAP];
    __shared__ float sex[4][CAP];
    __shared__ float swm[4][CAP];

    const int tid = threadIdx.x;
    const int w = tid >> 5, lane = tid & 31;
    const int row = blockIdx.x * 4 + w;
    const int b = row >> 12;

    unsigned count = g_cnt[row];
    if (count > CAP) count = CAP;
    float4* outp = (float4*)&Og[(size_t)row * Hn + lane * 4];
    if (count == 0) { *outp = make_float4(0.f, 0.f, 0.f, 0.f); return; }

    for (unsigned i = lane; i < count; i += 32)
        scol[w][i] = g_col[row * CAP + i];
    __syncwarp();

    float4 qv = *(const float4*)&Qg[(size_t)row * Hn + lane * 4];
    for (unsigned i = 0; i < count; i++) {
        unsigned col = scol[w][i];
        float4 kv = *(const float4*)&Kg[((size_t)(b * Vv + col)) * Hn + lane * 4];
        float d = qv.x * kv.x + qv.y * kv.y + qv.z * kv.z + qv.w * kv.w;
        #pragma unroll
        for (int o = 16; o > 0; o >>= 1)
            d += __shfl_xor_sync(0xffffffffu, d, o);
        if (lane == 0) sex[w][i] = d * SCALE_F;
    }
    __syncwarp();

    float M = -1e30f;
    for (unsigned i = lane; i < count; i += 32) M = fmaxf(M, sex[w][i]);
    #pragma unroll
    for (int o = 16; o > 0; o >>= 1)
        M = fmaxf(M, __shfl_xor_sync(0xffffffffu, M, o));

    float zp = 0.0f;
    for (unsigned i = lane; i < count; i += 32) {
        float e = __expf(sex[w][i] - M);
        zp += e;
        uint32_t j = (unsigned)row * 4096u + scol[w][i];
        swm[w][i] = keepf(j) ? e : 0.0f;
    }
    #pragma unroll
    for (int o = 16; o > 0; o >>= 1)
        zp += __shfl_xor_sync(0xffffffffu, zp, o);
    __syncwarp();

    float4 acc = make_float4(0.f, 0.f, 0.f, 0.f);
    for (unsigned i = 0; i < count; i++) {
        float wv = swm[w][i];
        if (wv != 0.0f) {
            float4 v = *(const float4*)&Vg[((size_t)(b * Vv + scol[w][i])) * Hn + lane * 4];
            acc.x += wv * v.x; acc.y += wv * v.y;
            acc.z += wv * v.z; acc.w += wv * v.w;
        }
    }
    float inv = 1.0f / (0.9f * zp);
    *outp = make_float4(acc.x * inv, acc.y * inv, acc.z * inv, acc.w * inv);
}

// ---------------- launcher ----------------------------------------------
extern "C" void kernel_launch(void* const* d_in, const int* in_sizes, int n_in,
                              void* d_out, int out_size) {
    const float* Qg = (const float*)d_in[0];
    const float* Kg = (const float*)d_in[1];
    const float* Vg = (const float*)d_in[2];
    float* Og = (float*)d_out;
    (void)in_sizes; (void)n_in; (void)out_size;

    cudaFuncSetAttribute(qk_kernel,
                         cudaFuncAttributeMaxDynamicSharedMemorySize, SMEM_QK);

    prep_kernel<<<512, 256>>>(Kg);
    dim3 gb(Qn / 128, Bn);
    qk_kernel<<<gb, 256, SMEM_QK>>>(Qg);
    pv_kernel<<<NROWS / 4, 128>>>(Qg, Kg, Vg, Og);
}